// round 3
// baseline (speedup 1.0000x reference)
#include <cuda_runtime.h>

// N=25000 nodes, E=400000 edges, D=32.
// out[i,h] = sum_{e: dst_e=i} msgs[e,h] + sum_d x[i,d]*node_W[h,d]
// msgs[e,h] = sum_k edge_attr[e,k] * Y[src_e, k*32+h]
// Y[j, k*32+h] = sum_d x[j,d] * W2[d, k*32+h],  W2[d, k*32+h] = edge_W[(d*32+h)*32 + k]

#define DD 32
#define N_MAX 25000
#define E_MAX 400000
#define KH 1024   // D*D

__device__ float g_Y[(size_t)N_MAX * KH];   // 102.4 MB
__device__ float g_W2[DD * KH];             // 128 KB
__device__ int   g_hist[N_MAX];
__device__ int   g_off[N_MAX];
__device__ int   g_cursor[N_MAX];
__device__ int   g_perm[E_MAX];
__device__ int   g_dsorted[E_MAX];

__device__ __forceinline__ void red_add_v4(float* addr, float4 v) {
    asm volatile("red.global.add.v4.f32 [%0], {%1,%2,%3,%4};"
                 :: "l"(addr), "f"(v.x), "f"(v.y), "f"(v.z), "f"(v.w)
                 : "memory");
}

// ---------------------------------------------------------------------------
// reorder edge_W [1024,32] -> W2 [32,1024]; also zero histogram.
// ---------------------------------------------------------------------------
__global__ void reorder_w_kernel(const float* __restrict__ edge_W, int N) {
    int idx = blockIdx.x * blockDim.x + threadIdx.x;
    if (idx < DD * KH) {
        int d  = idx >> 10;
        int kh = idx & (KH - 1);
        int k  = kh >> 5;
        int h  = kh & 31;
        g_W2[idx] = edge_W[(d * 32 + h) * 32 + k];
    }
    if (idx < N) g_hist[idx] = 0;
}

// ---------------------------------------------------------------------------
// histogram of src (4 edges / thread for fewer, wider loads)
// ---------------------------------------------------------------------------
__global__ void hist_kernel(const int* __restrict__ edge_index, int E) {
    int base = (blockIdx.x * blockDim.x + threadIdx.x) * 4;
    #pragma unroll
    for (int j = 0; j < 4; j++) {
        int e = base + j;
        if (e < E) atomicAdd(&g_hist[edge_index[e]], 1);
    }
}

// ---------------------------------------------------------------------------
// single-block exclusive scan: thread-serial chunk + warp scan + block scan.
// Writes g_off (CSR starts) and g_cursor (scatter cursors).
// ---------------------------------------------------------------------------
__global__ void scan_kernel(int N) {
    __shared__ int wsum[32];
    int t = threadIdx.x;                 // 1024 threads
    int C = (N + 1023) / 1024;
    int base = t * C;

    int total = 0;
    for (int j = 0; j < C; j++) {
        int i = base + j;
        if (i < N) total += g_hist[i];
    }
    int lane = t & 31, wid = t >> 5;
    int incl = total;
    #pragma unroll
    for (int off = 1; off < 32; off <<= 1) {
        int n = __shfl_up_sync(0xffffffffu, incl, off);
        if (lane >= off) incl += n;
    }
    if (lane == 31) wsum[wid] = incl;
    __syncthreads();
    if (wid == 0) {
        int s = wsum[lane];
        #pragma unroll
        for (int off = 1; off < 32; off <<= 1) {
            int n = __shfl_up_sync(0xffffffffu, s, off);
            if (lane >= off) s += n;
        }
        wsum[lane] = s;
    }
    __syncthreads();
    int run = ((wid == 0) ? 0 : wsum[wid - 1]) + incl - total; // thread-exclusive
    for (int j = 0; j < C; j++) {
        int i = base + j;
        if (i < N) {
            g_off[i]    = run;
            g_cursor[i] = run;
            run += g_hist[i];
        }
    }
}

// ---------------------------------------------------------------------------
// scatter edges into src-sorted order (2 independent chains / thread)
// ---------------------------------------------------------------------------
__global__ void scatter_kernel(const int* __restrict__ edge_index, int E) {
    int e0 = blockIdx.x * blockDim.x * 2 + threadIdx.x;
    int e1 = e0 + blockDim.x;
    int s0 = -1, s1 = -1, d0 = 0, d1 = 0;
    if (e0 < E) { s0 = edge_index[e0]; d0 = edge_index[E + e0]; }
    if (e1 < E) { s1 = edge_index[e1]; d1 = edge_index[E + e1]; }
    int p0 = (s0 >= 0) ? atomicAdd(&g_cursor[s0], 1) : 0;
    int p1 = (s1 >= 0) ? atomicAdd(&g_cursor[s1], 1) : 0;
    if (s0 >= 0) { g_perm[p0] = e0; g_dsorted[p0] = d0; }
    if (s1 >= 0) { g_perm[p1] = e1; g_dsorted[p1] = d1; }
}

// ---------------------------------------------------------------------------
// out[i,h] = sum_d x[i,d] * node_W[h,d]
// ---------------------------------------------------------------------------
__global__ void node_init_kernel(const float* __restrict__ x,
                                 const float* __restrict__ node_W,
                                 float* __restrict__ out, int N) {
    __shared__ float sWT[DD * DD];
    __shared__ float sx[8][DD];
    int t = threadIdx.x;
    for (int i = t; i < DD * DD; i += 256) {
        int h = i & 31, d = i >> 5;
        sWT[d * 32 + h] = node_W[h * 32 + d];
    }
    int node0 = blockIdx.x * 8;
    int r = t >> 5, h = t & 31;
    int node = node0 + r;
    if (node < N) sx[r][h] = x[node * DD + h];
    __syncthreads();
    if (node < N) {
        float acc = 0.f;
        #pragma unroll
        for (int d = 0; d < DD; d++) acc += sx[r][d] * sWT[d * 32 + h];
        out[node * DD + h] = acc;
    }
}

// ---------------------------------------------------------------------------
// Y = x @ W2   ([N,32] @ [32,1024])
// ---------------------------------------------------------------------------
__global__ void y_gemm_kernel(const float* __restrict__ x, int N) {
    __shared__ float4 sx4[32][9];
    int tx = threadIdx.x;
    int c  = blockIdx.x * 256 + tx;
    int r0 = blockIdx.y * 32;

    for (int i = tx; i < 32 * 8; i += 256) {
        int r = i >> 3, j = i & 7;
        float4 v = make_float4(0.f, 0.f, 0.f, 0.f);
        if (r0 + r < N) v = ((const float4*)x)[(size_t)(r0 + r) * 8 + j];
        sx4[r][j] = v;
    }
    __syncthreads();

    float w[DD];
    #pragma unroll
    for (int d = 0; d < DD; d++) w[d] = g_W2[d * KH + c];

    int rmax = N - r0; if (rmax > 32) rmax = 32;
    for (int r = 0; r < rmax; r++) {
        float a0 = 0.f, a1 = 0.f, a2 = 0.f, a3 = 0.f;
        #pragma unroll
        for (int j = 0; j < 8; j++) {
            float4 v = sx4[r][j];
            a0 += v.x * w[4 * j + 0];
            a1 += v.y * w[4 * j + 1];
            a2 += v.z * w[4 * j + 2];
            a3 += v.w * w[4 * j + 3];
        }
        g_Y[(size_t)(r0 + r) * KH + c] = (a0 + a1) + (a2 + a3);
    }
}

// ---------------------------------------------------------------------------
// CSR edge kernel: warp w owns source node w. Y row loaded ONCE into regs
// (lane = (k-group g, h-quad h4): y[i] = Y4[(8g+i)*8 + h4]). Per edge:
// 32 FFMA + butterfly reduce + one red.v4 from lanes 0-7.
// msg[h4*4+c] = sum_k ea[k] * Y[k*32 + h4*4 + c]
// ---------------------------------------------------------------------------
__global__ void edge_csr_kernel(const float* __restrict__ edge_attr,
                                float* __restrict__ out, int N) {
    int w    = (blockIdx.x * blockDim.x + threadIdx.x) >> 5;
    int lane = threadIdx.x & 31;
    if (w >= N) return;                 // warp-uniform
    int start = g_off[w];
    int cnt   = g_hist[w];
    if (cnt == 0) return;

    int g8 = lane & 24;                 // 8 * (lane/8)
    int h4 = lane & 7;
    const float4* Yrow = (const float4*)(g_Y + (size_t)w * KH);
    float4 y[8];
    #pragma unroll
    for (int i = 0; i < 8; i++) y[i] = Yrow[(g8 + i) * 8 + h4];

    for (int e = start; e < start + cnt; e++) {
        int pe  = g_perm[e];            // warp-uniform
        int dst = g_dsorted[e];         // warp-uniform
        float ea = edge_attr[(size_t)pe * DD + lane];
        float4 acc = make_float4(0.f, 0.f, 0.f, 0.f);
        #pragma unroll
        for (int i = 0; i < 8; i++) {
            float f = __shfl_sync(0xffffffffu, ea, g8 + i);
            acc.x += f * y[i].x;
            acc.y += f * y[i].y;
            acc.z += f * y[i].z;
            acc.w += f * y[i].w;
        }
        #pragma unroll
        for (int m = 8; m <= 16; m <<= 1) {
            acc.x += __shfl_xor_sync(0xffffffffu, acc.x, m);
            acc.y += __shfl_xor_sync(0xffffffffu, acc.y, m);
            acc.z += __shfl_xor_sync(0xffffffffu, acc.z, m);
            acc.w += __shfl_xor_sync(0xffffffffu, acc.w, m);
        }
        if (lane < 8) red_add_v4(&out[(size_t)dst * DD + h4 * 4], acc);
    }
}

// ---------------------------------------------------------------------------
// Launch.  inputs: 0:x[N*32] 1:edge_attr[E*32] 2:edge_W[1024*32] 3:node_W[32*32]
//          4:edge_index[2*E] i32.  out: [N*32] f32
// ---------------------------------------------------------------------------
extern "C" void kernel_launch(void* const* d_in, const int* in_sizes, int n_in,
                              void* d_out, int out_size) {
    const float* x         = (const float*)d_in[0];
    const float* edge_attr = (const float*)d_in[1];
    const float* edge_W    = (const float*)d_in[2];
    const float* node_W    = (const float*)d_in[3];
    const int*   edge_idx  = (const int*)  d_in[4];
    float* out = (float*)d_out;

    int N = in_sizes[0] / DD;
    int E = in_sizes[4] / 2;
    if (N > N_MAX) N = N_MAX;
    if (E > E_MAX) E = E_MAX;

    // 1. weight reorder + histogram zero
    reorder_w_kernel<<<(DD * KH + 255) / 256, 256>>>(edge_W, N);

    // 2. counting sort (CSR by src)
    hist_kernel<<<(E + 1023) / 1024, 256>>>(edge_idx, E);
    scan_kernel<<<1, 1024>>>(N);
    scatter_kernel<<<(E + 511) / 512, 256>>>(edge_idx, E);

    // 3. init output with node MLP term
    node_init_kernel<<<(N + 7) / 8, 256>>>(x, node_W, out, N);

    // 4. Y = x @ W2
    dim3 ygrid(KH / 256, (N + 31) / 32);
    y_gemm_kernel<<<ygrid, 256>>>(x, N);

    // 5. CSR edge messages + vector-red scatter
    edge_csr_kernel<<<(N * 32 + 255) / 256, 256>>>(edge_attr, out, N);
}

// round 4
// speedup vs baseline: 1.1916x; 1.1916x over previous
#include <cuda_runtime.h>

// N=25000 nodes, E=400000 edges, D=32.
// out[i,h] = sum_{e: dst_e=i} msgs[e,h] + sum_d x[i,d]*node_W[h,d]
// msgs[e,h] = sum_k edge_attr[e,k] * Y[src_e, k*32+h]
// Y[j, k*32+h] = sum_d x[j,d] * W2[d, k*32+h],  W2[d, k*32+h] = edge_W[(d*32+h)*32 + k]

#define DD 32
#define N_MAX 25000
#define E_MAX 400000
#define KH 1024   // D*D

__device__ float g_Y[(size_t)N_MAX * KH];   // 102.4 MB
__device__ float g_W2[DD * KH];             // 128 KB
__device__ int   g_hist[N_MAX];             // statically zero; re-zeroed by scan each call
__device__ int   g_cursor[N_MAX];
__device__ int   g_perm[E_MAX];
__device__ int   g_ssorted[E_MAX];
__device__ int   g_dsorted[E_MAX];

__device__ __forceinline__ void red_add_v4(float* addr, float4 v) {
    asm volatile("red.global.add.v4.f32 [%0], {%1,%2,%3,%4};"
                 :: "l"(addr), "f"(v.x), "f"(v.y), "f"(v.z), "f"(v.w)
                 : "memory");
}

// ---------------------------------------------------------------------------
// Launch 1: blocks [0,RE_B): reorder edge_W -> W2.  blocks [RE_B,..): src hist.
// (g_hist is zero on entry: statically at call 1, re-zeroed by scan_kernel after.)
// ---------------------------------------------------------------------------
__global__ void setup_kernel(const float* __restrict__ edge_W,
                             const int*   __restrict__ edge_index,
                             int E, int RE_B) {
    if (blockIdx.x < RE_B) {
        int idx = blockIdx.x * 256 + threadIdx.x;
        if (idx < DD * KH) {
            int d  = idx >> 10;
            int kh = idx & (KH - 1);
            int k  = kh >> 5;
            int h  = kh & 31;
            g_W2[idx] = edge_W[(d * 32 + h) * 32 + k];
        }
    } else {
        int base = ((blockIdx.x - RE_B) * 256 + threadIdx.x) * 4;
        #pragma unroll
        for (int j = 0; j < 4; j++) {
            int e = base + j;
            if (e < E) atomicAdd(&g_hist[edge_index[e]], 1);
        }
    }
}

// ---------------------------------------------------------------------------
// Launch 2: single-block exclusive scan -> g_cursor; zeroes g_hist after use.
// ---------------------------------------------------------------------------
__global__ void scan_kernel(int N) {
    __shared__ int wsum[32];
    int t = threadIdx.x;                 // 1024 threads
    int C = (N + 1023) / 1024;
    int base = t * C;

    int total = 0;
    for (int j = 0; j < C; j++) {
        int i = base + j;
        if (i < N) total += g_hist[i];
    }
    int lane = t & 31, wid = t >> 5;
    int incl = total;
    #pragma unroll
    for (int off = 1; off < 32; off <<= 1) {
        int n = __shfl_up_sync(0xffffffffu, incl, off);
        if (lane >= off) incl += n;
    }
    if (lane == 31) wsum[wid] = incl;
    __syncthreads();
    if (wid == 0) {
        int s = wsum[lane];
        #pragma unroll
        for (int off = 1; off < 32; off <<= 1) {
            int n = __shfl_up_sync(0xffffffffu, s, off);
            if (lane >= off) s += n;
        }
        wsum[lane] = s;
    }
    __syncthreads();
    int run = ((wid == 0) ? 0 : wsum[wid - 1]) + incl - total; // thread-exclusive
    for (int j = 0; j < C; j++) {
        int i = base + j;
        if (i < N) {
            g_cursor[i] = run;
            run += g_hist[i];
            g_hist[i] = 0;   // ready for next graph replay
        }
    }
}

// ---------------------------------------------------------------------------
// Launch 3: mega-kernel. Block ranges: [0,SCAT_B) scatter | [..,+GEMM_B) Y-gemm
// | rest: node_init. The three are mutually independent.
// ---------------------------------------------------------------------------
__global__ void mega_kernel(const int*   __restrict__ edge_index,
                            const float* __restrict__ x,
                            const float* __restrict__ node_W,
                            float* __restrict__ out,
                            int N, int E, int SCAT_B, int GEMM_B) {
    __shared__ union {
        float4 sx4[32][9];
        struct { float sWT[DD * DD]; float sx[8][DD]; } n;
    } sm;
    int bx = blockIdx.x;
    int tx = threadIdx.x;

    if (bx < SCAT_B) {
        // ---- scatter edges into src-sorted order (2 per thread) ----
        int e0 = bx * 512 + tx;
        int e1 = e0 + 256;
        int s0 = -1, s1 = -1, d0 = 0, d1 = 0;
        if (e0 < E) { s0 = edge_index[e0]; d0 = edge_index[E + e0]; }
        if (e1 < E) { s1 = edge_index[e1]; d1 = edge_index[E + e1]; }
        int p0 = (s0 >= 0) ? atomicAdd(&g_cursor[s0], 1) : 0;
        int p1 = (s1 >= 0) ? atomicAdd(&g_cursor[s1], 1) : 0;
        if (s0 >= 0) { g_perm[p0] = e0; g_ssorted[p0] = s0; g_dsorted[p0] = d0; }
        if (s1 >= 0) { g_perm[p1] = e1; g_ssorted[p1] = s1; g_dsorted[p1] = d1; }
    } else if (bx < SCAT_B + GEMM_B) {
        // ---- Y = x @ W2 : tile of 32 rows x 256 cols ----
        int gb = bx - SCAT_B;
        int c  = (gb & 3) * 256 + tx;
        int r0 = (gb >> 2) * 32;

        for (int i = tx; i < 32 * 8; i += 256) {
            int r = i >> 3, j = i & 7;
            float4 v = make_float4(0.f, 0.f, 0.f, 0.f);
            if (r0 + r < N) v = ((const float4*)x)[(size_t)(r0 + r) * 8 + j];
            sm.sx4[r][j] = v;
        }
        __syncthreads();

        float w[DD];
        #pragma unroll
        for (int d = 0; d < DD; d++) w[d] = g_W2[d * KH + c];

        int rmax = N - r0; if (rmax > 32) rmax = 32;
        for (int r = 0; r < rmax; r++) {
            float a0 = 0.f, a1 = 0.f, a2 = 0.f, a3 = 0.f;
            #pragma unroll
            for (int j = 0; j < 8; j++) {
                float4 v = sm.sx4[r][j];
                a0 += v.x * w[4 * j + 0];
                a1 += v.y * w[4 * j + 1];
                a2 += v.z * w[4 * j + 2];
                a3 += v.w * w[4 * j + 3];
            }
            g_Y[(size_t)(r0 + r) * KH + c] = (a0 + a1) + (a2 + a3);
        }
    } else {
        // ---- out[i,h] = sum_d x[i,d] * node_W[h,d] ----
        int nb = bx - SCAT_B - GEMM_B;
        for (int i = tx; i < DD * DD; i += 256) {
            int h = i & 31, d = i >> 5;
            sm.n.sWT[d * 32 + h] = node_W[h * 32 + d];
        }
        int node0 = nb * 8;
        int r = tx >> 5, h = tx & 31;
        int node = node0 + r;
        if (node < N) sm.n.sx[r][h] = x[node * DD + h];
        __syncthreads();
        if (node < N) {
            float acc = 0.f;
            #pragma unroll
            for (int d = 0; d < DD; d++) acc += sm.n.sx[r][d] * sm.n.sWT[d * 32 + h];
            out[node * DD + h] = acc;
        }
    }
}

// ---------------------------------------------------------------------------
// Launch 4: edge messages. Warp owns 16 consecutive src-sorted edges.
// lane = (k-group g8, h-quad h4). Y row register-cached across same-src runs.
// Per edge: 8 bcast shfl + 8 float4 FMA + 8 reduce shfl + red.v4 (lanes 0-7).
// ---------------------------------------------------------------------------
__global__ void edge_kernel16(const float* __restrict__ edge_attr,
                              float* __restrict__ out, int E) {
    int w    = (blockIdx.x * blockDim.x + threadIdx.x) >> 5;
    int lane = threadIdx.x & 31;
    int e0 = w * 16;
    if (e0 >= E) return;                 // warp-uniform
    int cnt = E - e0; if (cnt > 16) cnt = 16;

    // lane-parallel metadata prefetch (lane i holds edge e0+i's info)
    int p = 0, dv = 0, sv = -1;
    if (lane < cnt) {
        p  = g_perm[e0 + lane];
        dv = g_dsorted[e0 + lane];
        sv = g_ssorted[e0 + lane];
    }
    // prefetch edge_attr: ea[i] = edge_attr[perm[e0+i]*32 + lane] (16-deep MLP)
    float ea[16];
    #pragma unroll
    for (int i = 0; i < 16; i++) {
        int pi = __shfl_sync(0xffffffffu, p, i);
        if (i < cnt) ea[i] = edge_attr[(size_t)pi * DD + lane];
    }

    int g8 = lane & 24;      // k-group base (0,8,16,24)
    int h4 = lane & 7;       // h-quad index
    float4 y[8];
    int prev = -1;
    #pragma unroll
    for (int i = 0; i < 16; i++) {
        if (i < cnt) {
            int s = __shfl_sync(0xffffffffu, sv, i);
            if (s != prev) {
                const float4* Yrow = (const float4*)(g_Y + (size_t)s * KH);
                #pragma unroll
                for (int j = 0; j < 8; j++) y[j] = Yrow[(g8 + j) * 8 + h4];
                prev = s;
            }
            float4 acc = make_float4(0.f, 0.f, 0.f, 0.f);
            #pragma unroll
            for (int j = 0; j < 8; j++) {
                float f = __shfl_sync(0xffffffffu, ea[i], g8 + j);
                acc.x += f * y[j].x;
                acc.y += f * y[j].y;
                acc.z += f * y[j].z;
                acc.w += f * y[j].w;
            }
            #pragma unroll
            for (int m = 8; m <= 16; m <<= 1) {
                acc.x += __shfl_xor_sync(0xffffffffu, acc.x, m);
                acc.y += __shfl_xor_sync(0xffffffffu, acc.y, m);
                acc.z += __shfl_xor_sync(0xffffffffu, acc.z, m);
                acc.w += __shfl_xor_sync(0xffffffffu, acc.w, m);
            }
            int dst = __shfl_sync(0xffffffffu, dv, i);
            if (lane < 8) red_add_v4(&out[(size_t)dst * DD + h4 * 4], acc);
        }
    }
}

// ---------------------------------------------------------------------------
// Launch.  inputs: 0:x[N*32] 1:edge_attr[E*32] 2:edge_W[1024*32] 3:node_W[32*32]
//          4:edge_index[2*E] i32.  out: [N*32] f32
// ---------------------------------------------------------------------------
extern "C" void kernel_launch(void* const* d_in, const int* in_sizes, int n_in,
                              void* d_out, int out_size) {
    const float* x         = (const float*)d_in[0];
    const float* edge_attr = (const float*)d_in[1];
    const float* edge_W    = (const float*)d_in[2];
    const float* node_W    = (const float*)d_in[3];
    const int*   edge_idx  = (const int*)  d_in[4];
    float* out = (float*)d_out;

    int N = in_sizes[0] / DD;
    int E = in_sizes[4] / 2;
    if (N > N_MAX) N = N_MAX;
    if (E > E_MAX) E = E_MAX;

    // 1. weight reorder + src histogram
    int RE_B   = (DD * KH + 255) / 256;         // 128
    int HIST_B = ((E + 3) / 4 + 255) / 256;
    setup_kernel<<<RE_B + HIST_B, 256>>>(edge_W, edge_idx, E, RE_B);

    // 2. scan (cursors) + hist re-zero
    scan_kernel<<<1, 1024>>>(N);

    // 3. scatter | Y-gemm | node_init (independent, fused into one launch)
    int SCAT_B = (E + 511) / 512;
    int GEMM_B = 4 * ((N + 31) / 32);
    int NODE_B = (N + 7) / 8;
    mega_kernel<<<SCAT_B + GEMM_B + NODE_B, 256>>>(edge_idx, x, node_W, out,
                                                   N, E, SCAT_B, GEMM_B);

    // 4. edge messages + vector-red scatter
    int nwarps = (E + 15) / 16;
    edge_kernel16<<<(nwarps * 32 + 255) / 256, 256>>>(edge_attr, out, E);
}

// round 5
// speedup vs baseline: 1.5056x; 1.2635x over previous
#include <cuda_runtime.h>
#include <cstdint>

// N=25000 nodes, E=400000 edges, D=32.
// out[i,h] = sum_{e: dst_e=i} msgs[e,h] + sum_d x[i,d]*node_W[h,d]
// msgs[e,h] = sum_k edge_attr[e,k] * Y[src_e, k*32+h]
// Y[j, c]   = sum_d x[j,d] * W2[d,c],  W2[d, k*32+h] = edge_W[(d*32+h)*32 + k]

#define DD 32
#define N_MAX 25000
#define E_MAX 400000
#define KH 1024   // D*D

__device__ float g_Y[(size_t)N_MAX * KH];     // 102.4 MB
__device__ float g_Bfh[32768];                // tf32-hi B fragments (frag-order)
__device__ float g_Bfl[32768];                // tf32-lo B fragments
__device__ int   g_hist[N_MAX];               // zero at entry; re-zeroed by scan
__device__ int   g_cursor[N_MAX];
__device__ int   g_perm[E_MAX + 16];
__device__ int   g_ssorted[E_MAX + 16];
__device__ int   g_dsorted[E_MAX + 16];

__device__ __forceinline__ void red_add_v4(float* addr, float4 v) {
    asm volatile("red.global.add.v4.f32 [%0], {%1,%2,%3,%4};"
                 :: "l"(addr), "f"(v.x), "f"(v.y), "f"(v.z), "f"(v.w)
                 : "memory");
}

__device__ __forceinline__ void mma_tf32(float* c, const unsigned* a,
                                         unsigned b0, unsigned b1) {
    asm volatile(
        "mma.sync.aligned.m16n8k8.row.col.f32.tf32.tf32.f32 "
        "{%0,%1,%2,%3}, {%4,%5,%6,%7}, {%8,%9}, {%0,%1,%2,%3};"
        : "+f"(c[0]), "+f"(c[1]), "+f"(c[2]), "+f"(c[3])
        : "r"(a[0]), "r"(a[1]), "r"(a[2]), "r"(a[3]), "r"(b0), "r"(b1));
}

__device__ __forceinline__ void split_tf32(float v, unsigned& hi, unsigned& lo) {
    unsigned u = __float_as_uint(v) & 0xFFFFE000u;
    hi = u;
    lo = __float_as_uint(v - __uint_as_float(u));
}

// ---------------------------------------------------------------------------
// Launch 1: blocks [0,BF_B): precompute tf32 B-fragments from edge_W (+pad fill)
//           blocks [BF_B,..): src histogram
// B-frag layout: idx = ((nt*4 + ks)*32 + lane)*2 + reg; nt in [0,128), ks in [0,4).
//   d = ks*8 + reg*4 + (lane&3); c = nt*8 + (lane>>2);
//   W2[d][c] = edge_W[(d*32 + (c&31))*32 + (c>>5)]
// ---------------------------------------------------------------------------
__global__ void setup_kernel(const float* __restrict__ edge_W,
                             const int*   __restrict__ edge_index,
                             int E, int BF_B) {
    if (blockIdx.x < BF_B) {
        int idx = blockIdx.x * 256 + threadIdx.x;
        if (idx < 32768) {
            int reg  = idx & 1;
            int lane = (idx >> 1) & 31;
            int ks   = (idx >> 6) & 3;
            int nt   = idx >> 8;
            int d = ks * 8 + reg * 4 + (lane & 3);
            int c = nt * 8 + (lane >> 2);
            float w = edge_W[(d * 32 + (c & 31)) * 32 + (c >> 5)];
            unsigned hi, lo;
            split_tf32(w, hi, lo);
            g_Bfh[idx] = __uint_as_float(hi);
            g_Bfl[idx] = __uint_as_float(lo);
        }
        if (blockIdx.x == 0 && threadIdx.x < 16) {
            int e = E + threadIdx.x;   // pad region for the edge kernel
            g_perm[e] = 0; g_ssorted[e] = 0; g_dsorted[e] = 0;
        }
    } else {
        int base = ((blockIdx.x - BF_B) * 256 + threadIdx.x) * 4;
        #pragma unroll
        for (int j = 0; j < 4; j++) {
            int e = base + j;
            if (e < E) atomicAdd(&g_hist[edge_index[e]], 1);
        }
    }
}

// ---------------------------------------------------------------------------
// Launch 2: single-block exclusive scan -> g_cursor; re-zeroes g_hist.
// ---------------------------------------------------------------------------
__global__ void scan_kernel(int N) {
    __shared__ int wsum[32];
    int t = threadIdx.x;                 // 1024 threads
    int C = (N + 1023) / 1024;
    int base = t * C;

    int total = 0;
    for (int j = 0; j < C; j++) {
        int i = base + j;
        if (i < N) total += g_hist[i];
    }
    int lane = t & 31, wid = t >> 5;
    int incl = total;
    #pragma unroll
    for (int off = 1; off < 32; off <<= 1) {
        int n = __shfl_up_sync(0xffffffffu, incl, off);
        if (lane >= off) incl += n;
    }
    if (lane == 31) wsum[wid] = incl;
    __syncthreads();
    if (wid == 0) {
        int s = wsum[lane];
        #pragma unroll
        for (int off = 1; off < 32; off <<= 1) {
            int n = __shfl_up_sync(0xffffffffu, s, off);
            if (lane >= off) s += n;
        }
        wsum[lane] = s;
    }
    __syncthreads();
    int run = ((wid == 0) ? 0 : wsum[wid - 1]) + incl - total;
    for (int j = 0; j < C; j++) {
        int i = base + j;
        if (i < N) {
            g_cursor[i] = run;
            run += g_hist[i];
            g_hist[i] = 0;
        }
    }
}

// ---------------------------------------------------------------------------
// Launch 3: mega-kernel. [0,SCAT_B) scatter | [..,+GEMM_B) tf32 Y-gemm | node.
// gemm block: 1024 rows x 64 cols; warp = 128 rows, inner pairs of m16 tiles.
// ---------------------------------------------------------------------------
__global__ void mega_kernel(const int*   __restrict__ edge_index,
                            const float* __restrict__ x,
                            const float* __restrict__ node_W,
                            float* __restrict__ out,
                            int N, int E, int SCAT_B, int GEMM_B) {
    __shared__ union {
        float4 sBf[8][4][32];                                    // 16 KB
        struct { float sWT[DD * DD]; float sx[8][DD]; } n;
    } sm;
    int bx = blockIdx.x;
    int tx = threadIdx.x;

    if (bx < SCAT_B) {
        // ---- scatter edges into src-sorted order (2 per thread) ----
        int e0 = bx * 512 + tx;
        int e1 = e0 + 256;
        int s0 = -1, s1 = -1, d0 = 0, d1 = 0;
        if (e0 < E) { s0 = edge_index[e0]; d0 = edge_index[E + e0]; }
        if (e1 < E) { s1 = edge_index[e1]; d1 = edge_index[E + e1]; }
        int p0 = (s0 >= 0) ? atomicAdd(&g_cursor[s0], 1) : 0;
        int p1 = (s1 >= 0) ? atomicAdd(&g_cursor[s1], 1) : 0;
        if (s0 >= 0) { g_perm[p0] = e0; g_ssorted[p0] = s0; g_dsorted[p0] = d0; }
        if (s1 >= 0) { g_perm[p1] = e1; g_ssorted[p1] = s1; g_dsorted[p1] = d1; }
    } else if (bx < SCAT_B + GEMM_B) {
        // ---- Y = x @ W2 via tf32 MMA, 3-pass hi/lo ----
        int gb = bx - SCAT_B;
        int mb = gb >> 4;
        int cb = gb & 15;
        int c0 = cb * 64;

        // stage B fragments: float4(bh0,bh1,bl0,bl1)
        for (int i = tx; i < 1024; i += 256) {
            float2 h = ((const float2*)g_Bfh)[cb * 1024 + i];
            float2 l = ((const float2*)g_Bfl)[cb * 1024 + i];
            int lane_ = i & 31, ks_ = (i >> 5) & 3, nt_ = i >> 7;
            sm.sBf[nt_][ks_][lane_] = make_float4(h.x, h.y, l.x, l.y);
        }
        __syncthreads();

        int w = tx >> 5, lane = tx & 31;
        int gid = lane >> 2, tig = lane & 3;
        int Nc = N - 1;

        for (int mp = 0; mp < 4; mp++) {
            int rbase = mb * 1024 + w * 128 + mp * 32;
            float C[2][8][4];
            #pragma unroll
            for (int m2 = 0; m2 < 2; m2++)
                #pragma unroll
                for (int nt = 0; nt < 8; nt++)
                    #pragma unroll
                    for (int r = 0; r < 4; r++) C[m2][nt][r] = 0.f;

            #pragma unroll
            for (int ks = 0; ks < 4; ks++) {
                unsigned ah[2][4], al[2][4];
                #pragma unroll
                for (int m2 = 0; m2 < 2; m2++) {
                    int rA  = rbase + m2 * 16;
                    int ra0 = min(rA + gid, Nc);
                    int ra1 = min(rA + gid + 8, Nc);
                    float v0 = x[ra0 * 32 + ks * 8 + tig];
                    float v1 = x[ra1 * 32 + ks * 8 + tig];
                    float v2 = x[ra0 * 32 + ks * 8 + tig + 4];
                    float v3 = x[ra1 * 32 + ks * 8 + tig + 4];
                    split_tf32(v0, ah[m2][0], al[m2][0]);
                    split_tf32(v1, ah[m2][1], al[m2][1]);
                    split_tf32(v2, ah[m2][2], al[m2][2]);
                    split_tf32(v3, ah[m2][3], al[m2][3]);
                }
                #pragma unroll
                for (int nt = 0; nt < 8; nt++) {
                    float4 b = sm.sBf[nt][ks][lane];
                    unsigned bh0 = __float_as_uint(b.x), bh1 = __float_as_uint(b.y);
                    unsigned bl0 = __float_as_uint(b.z), bl1 = __float_as_uint(b.w);
                    #pragma unroll
                    for (int m2 = 0; m2 < 2; m2++) {
                        mma_tf32(C[m2][nt], ah[m2], bh0, bh1);
                        mma_tf32(C[m2][nt], al[m2], bh0, bh1);
                        mma_tf32(C[m2][nt], ah[m2], bl0, bl1);
                    }
                }
            }
            // store
            #pragma unroll
            for (int m2 = 0; m2 < 2; m2++) {
                int rA  = rbase + m2 * 16;
                int r0s = rA + gid, r1s = r0s + 8;
                #pragma unroll
                for (int nt = 0; nt < 8; nt++) {
                    int c = c0 + nt * 8 + 2 * tig;
                    if (r0s < N)
                        *(float2*)&g_Y[(size_t)r0s * KH + c] =
                            make_float2(C[m2][nt][0], C[m2][nt][1]);
                    if (r1s < N)
                        *(float2*)&g_Y[(size_t)r1s * KH + c] =
                            make_float2(C[m2][nt][2], C[m2][nt][3]);
                }
            }
        }
    } else {
        // ---- out[i,h] = sum_d x[i,d] * node_W[h,d]  (32 nodes/block) ----
        int nb = bx - SCAT_B - GEMM_B;
        for (int i = tx; i < DD * DD; i += 256) {
            int h = i & 31, d = i >> 5;
            sm.n.sWT[d * 32 + h] = node_W[h * 32 + d];
        }
        __syncthreads();
        int r = tx >> 5, h = tx & 31;
        for (int it = 0; it < 4; it++) {
            int node = nb * 32 + it * 8 + r;
            if (node < N) sm.n.sx[r][h] = x[node * DD + h];
            __syncthreads();
            if (node < N) {
                float acc = 0.f;
                #pragma unroll
                for (int d = 0; d < DD; d++)
                    acc += sm.n.sx[r][d] * sm.n.sWT[d * 32 + h];
                out[node * DD + h] = acc;
            }
            __syncthreads();
        }
    }
}

// ---------------------------------------------------------------------------
// Launch 4: edge messages, branch-light. Warp = 16 sorted edges.
// edge_attr staged in SMEM (pitch 36 -> conflict-free LDS.128 of 8 multipliers).
// Runs of equal src found via ballot; Y row in 32 regs per run.
// Reduction: xor-8 (4 shfl) + 16-lane red.v4 (2 partials per address).
// ---------------------------------------------------------------------------
__global__ void edge_kernel16(const float* __restrict__ edge_attr,
                              float* __restrict__ out, int E) {
    __shared__ float eas[8][16 * 36];   // 18 KB
    int w    = threadIdx.x >> 5;
    int lane = threadIdx.x & 31;
    int gw = blockIdx.x * 8 + w;
    int e0 = gw * 16;
    if (e0 >= E) return;                 // warp-uniform

    int p16 = 0, s16 = 0, d16 = 0;
    if (lane < 16) {
        p16 = g_perm[e0 + lane];         // padded region is valid for e>=E
        s16 = g_ssorted[e0 + lane];
        d16 = g_dsorted[e0 + lane];
    }
    // stage edge_attr rows (zero for padded edges)
    float* easw = &eas[w][0];
    #pragma unroll
    for (int i = 0; i < 16; i++) {
        int pi = __shfl_sync(0xffffffffu, p16, i);
        float v = 0.f;
        if (e0 + i < E) v = edge_attr[(size_t)pi * DD + lane];
        easw[i * 36 + lane] = v;
    }
    __syncwarp();

    // same-src run starts among the 16 edges
    int prevs = __shfl_up_sync(0xffffffffu, s16, 1);
    bool isStart = (lane == 0) || (s16 != prevs);
    unsigned startm = __ballot_sync(0xffffffffu, isStart && (lane < 16));

    int g8 = lane & 24;      // k-group base
    int h4 = lane & 7;       // h-quad index
    while (startm) {
        int i = __ffs(startm) - 1;
        startm &= startm - 1;
        int nxt = startm ? (__ffs(startm) - 1) : 16;
        int s = __shfl_sync(0xffffffffu, s16, i);
        const float4* Yrow = (const float4*)(g_Y + (size_t)s * KH);
        float4 y[8];
        #pragma unroll
        for (int j = 0; j < 8; j++) y[j] = Yrow[(g8 + j) * 8 + h4];

        for (int e = i; e < nxt; e++) {
            const float4* ep = (const float4*)(easw + e * 36 + g8);
            float4 f0 = ep[0];
            float4 f1 = ep[1];
            float4 acc;
            acc.x = f0.x * y[0].x; acc.y = f0.x * y[0].y;
            acc.z = f0.x * y[0].z; acc.w = f0.x * y[0].w;
            acc.x += f0.y * y[1].x; acc.y += f0.y * y[1].y;
            acc.z += f0.y * y[1].z; acc.w += f0.y * y[1].w;
            acc.x += f0.z * y[2].x; acc.y += f0.z * y[2].y;
            acc.z += f0.z * y[2].z; acc.w += f0.z * y[2].w;
            acc.x += f0.w * y[3].x; acc.y += f0.w * y[3].y;
            acc.z += f0.w * y[3].z; acc.w += f0.w * y[3].w;
            acc.x += f1.x * y[4].x; acc.y += f1.x * y[4].y;
            acc.z += f1.x * y[4].z; acc.w += f1.x * y[4].w;
            acc.x += f1.y * y[5].x; acc.y += f1.y * y[5].y;
            acc.z += f1.y * y[5].z; acc.w += f1.y * y[5].w;
            acc.x += f1.z * y[6].x; acc.y += f1.z * y[6].y;
            acc.z += f1.z * y[6].z; acc.w += f1.z * y[6].w;
            acc.x += f1.w * y[7].x; acc.y += f1.w * y[7].y;
            acc.z += f1.w * y[7].z; acc.w += f1.w * y[7].w;
            // combine k-group partners (0<->8, 16<->24)
            acc.x += __shfl_xor_sync(0xffffffffu, acc.x, 8);
            acc.y += __shfl_xor_sync(0xffffffffu, acc.y, 8);
            acc.z += __shfl_xor_sync(0xffffffffu, acc.z, 8);
            acc.w += __shfl_xor_sync(0xffffffffu, acc.w, 8);
            int dst = __shfl_sync(0xffffffffu, d16, e);
            if (!(lane & 8))
                red_add_v4(&out[(size_t)dst * DD + h4 * 4], acc);
        }
    }
}

// ---------------------------------------------------------------------------
// Launch.  inputs: 0:x[N*32] 1:edge_attr[E*32] 2:edge_W[1024*32] 3:node_W[32*32]
//          4:edge_index[2*E] i32.  out: [N*32] f32
// ---------------------------------------------------------------------------
extern "C" void kernel_launch(void* const* d_in, const int* in_sizes, int n_in,
                              void* d_out, int out_size) {
    const float* x         = (const float*)d_in[0];
    const float* edge_attr = (const float*)d_in[1];
    const float* edge_W    = (const float*)d_in[2];
    const float* node_W    = (const float*)d_in[3];
    const int*   edge_idx  = (const int*)  d_in[4];
    float* out = (float*)d_out;

    int N = in_sizes[0] / DD;
    int E = in_sizes[4] / 2;
    if (N > N_MAX) N = N_MAX;
    if (E > E_MAX) E = E_MAX;

    // 1. B-fragment precompute + pad fill + src histogram
    int BF_B   = 32768 / 256;                   // 128
    int HIST_B = ((E + 3) / 4 + 255) / 256;
    setup_kernel<<<BF_B + HIST_B, 256>>>(edge_W, edge_idx, E, BF_B);

    // 2. scan -> cursors (+ hist re-zero for graph replay)
    scan_kernel<<<1, 1024>>>(N);

    // 3. scatter | tf32 Y-gemm | node_init
    int SCAT_B = (E + 511) / 512;
    int MB     = (N + 1023) / 1024;
    int GEMM_B = MB * 16;
    int NODE_B = (N + 31) / 32;
    mega_kernel<<<SCAT_B + GEMM_B + NODE_B, 256>>>(edge_idx, x, node_W, out,
                                                   N, E, SCAT_B, GEMM_B);

    // 4. edge messages + vector-red scatter
    int nwarps = (E + 15) / 16;
    edge_kernel16<<<(nwarps + 7) / 8, 256>>>(edge_attr, out, E);
}